// round 2
// baseline (speedup 1.0000x reference)
#include <cuda_runtime.h>
#include <cstdint>

// Problem constants
#define BB      32768              // N*T
#define VNODES  10
#define CH      128
#define O3      384                // 3*INNER
#define NHEADS  8
#define DHEAD   16
#define ROWS    (BB*VNODES)        // 327680
#define STAT_BLOCKS 1024
#define ROWS_PER_STAT (ROWS/STAT_BLOCKS)   // 320

// Fused kernel tiling
#define BPB     8                  // graphs per block
#define MROWS   (BPB*VNODES)       // 80
#define THREADS 512

// smem layout (floats)
#define SM_YS   0                  // 80*128  (reused as attention output)
#define SM_QS   10240              // 80*384
#define SM_WS   40960              // 32*384
#define SM_MSK  53248              // 128 (100 used)
#define SM_AB   53376              // 256
#define SM_BO   53632              // 128
#define SM_FLOATS 53760
#define SM_BYTES  (SM_FLOATS*4)    // 215040

__device__ float g_part[STAT_BLOCKS * 256];   // per-block [sum(128), sumsq(128)]
__device__ float g_ab[2 * CH];                // a = gamma*rsqrt(var+eps), b = beta - mean*a

// ---------- packed f32x2 helpers ----------
__device__ __forceinline__ unsigned long long pack2(float lo, float hi) {
    unsigned long long r;
    asm("mov.b64 %0, {%1, %2};" : "=l"(r) : "f"(lo), "f"(hi));
    return r;
}
__device__ __forceinline__ void unpack2(unsigned long long v, float& lo, float& hi) {
    asm("mov.b64 {%0, %1}, %2;" : "=f"(lo), "=f"(hi) : "l"(v));
}
__device__ __forceinline__ unsigned long long ffma2(unsigned long long a,
                                                    unsigned long long b,
                                                    unsigned long long c) {
    unsigned long long d;
    asm("fma.rn.f32x2 %0, %1, %2, %3;" : "=l"(d) : "l"(a), "l"(b), "l"(c));
    return d;
}

// ---------- K1: per-block partial BN stats ----------
__global__ void __launch_bounds__(128) stats_partial(const float* __restrict__ x) {
    int c = threadIdx.x;                       // channel 0..127
    size_t r0 = (size_t)blockIdx.x * ROWS_PER_STAT;
    const float* p = x + r0 * CH + c;
    float s = 0.f, ss = 0.f;
    #pragma unroll 8
    for (int r = 0; r < ROWS_PER_STAT; r++) {
        float v = p[(size_t)r * CH];
        s += v;
        ss += v * v;
    }
    g_part[blockIdx.x * 256 + c]       = s;
    g_part[blockIdx.x * 256 + 128 + c] = ss;
}

// ---------- K2: finalize stats -> scale/shift ----------
__global__ void __launch_bounds__(128) stats_final(const float* __restrict__ gamma,
                                                   const float* __restrict__ beta) {
    int c = threadIdx.x;
    float s0 = 0.f, s1 = 0.f, q0 = 0.f, q1 = 0.f;
    for (int b = 0; b < STAT_BLOCKS; b += 2) {
        s0 += g_part[b * 256 + c];
        q0 += g_part[b * 256 + 128 + c];
        s1 += g_part[(b + 1) * 256 + c];
        q1 += g_part[(b + 1) * 256 + 128 + c];
    }
    float s = s0 + s1, ss = q0 + q1;
    const float invN = 1.0f / (float)ROWS;
    float mean = s * invN;
    float var  = ss * invN - mean * mean;
    float a = gamma[c] * rsqrtf(var + 1e-5f);
    g_ab[c]      = a;
    g_ab[CH + c] = beta[c] - mean * a;
}

// ---------- K3: fused BN + QKV + attention + out-proj ----------
__global__ void __launch_bounds__(THREADS, 1) fused_kernel(
    const float* __restrict__ x,
    const float* __restrict__ w_qkv,
    const float* __restrict__ w_out,
    const float* __restrict__ b_out,
    const float* __restrict__ mask,
    float* __restrict__ out)
{
    extern __shared__ float sm[];
    float* ys  = sm + SM_YS;    // 80x128, later reused as attention output
    float* qs  = sm + SM_QS;    // 80x384
    float* ws  = sm + SM_WS;    // 32x384 weight stage
    float* msk = sm + SM_MSK;
    float* ab  = sm + SM_AB;
    float* bo  = sm + SM_BO;

    const int tid = threadIdx.x;
    const size_t row0 = (size_t)blockIdx.x * MROWS;

    // small constants into smem
    if (tid < 256)                 ab[tid]        = g_ab[tid];
    else if (tid < 356)            msk[tid - 256] = mask[tid - 256];
    else if (tid >= 384)           bo[tid - 384]  = b_out[tid - 384];
    __syncthreads();

    // ---- BN-transformed load: ys[80][128] ----
    {
        const float* xb = x + row0 * CH;
        #pragma unroll 4
        for (int i = 0; i < (MROWS * CH) / THREADS; i++) {   // 20 iters
            int idx = tid + i * THREADS;
            int c = idx & (CH - 1);
            ys[idx] = xb[idx] * ab[c] + ab[CH + c];
        }
    }

    const int rg = tid >> 5;   // 0..15: rows rg + 16*q
    const int cp = tid & 31;   // col-pair cp + 32*p

    // ---- QKV GEMM: qs[80][384] = ys[80][128] @ w_qkv[128][384] ----
    {
        unsigned long long acc[5][6];
        #pragma unroll
        for (int q = 0; q < 5; q++)
            #pragma unroll
            for (int p = 0; p < 6; p++) acc[q][p] = 0ull;

        for (int kk = 0; kk < 4; kk++) {
            __syncthreads();   // ws reuse barrier (also covers BN-load before first use)
            #pragma unroll
            for (int i = 0; i < (32 * O3) / THREADS; i++) {  // 24 iters
                int idx = tid + i * THREADS;
                ws[idx] = w_qkv[kk * 32 * O3 + idx];
            }
            __syncthreads();

            #pragma unroll 4
            for (int k = 0; k < 32; k++) {
                unsigned long long yv[5];
                #pragma unroll
                for (int q = 0; q < 5; q++) {
                    float v = ys[(rg + 16 * q) * CH + kk * 32 + k];
                    yv[q] = pack2(v, v);
                }
                #pragma unroll
                for (int p = 0; p < 6; p++) {
                    unsigned long long wv =
                        *(const unsigned long long*)&ws[k * O3 + 2 * (cp + 32 * p)];
                    #pragma unroll
                    for (int q = 0; q < 5; q++) acc[q][p] = ffma2(yv[q], wv, acc[q][p]);
                }
            }
        }
        #pragma unroll
        for (int q = 0; q < 5; q++)
            #pragma unroll
            for (int p = 0; p < 6; p++)
                *(unsigned long long*)&qs[(rg + 16 * q) * O3 + 2 * (cp + 32 * p)] = acc[q][p];
    }
    __syncthreads();

    // ---- attention: 8 graphs x 8 heads x 10 q-rows = 640 tasks ----
    {
        const float scale = 0.25f;   // DH^-0.5
        for (int tt = tid; tt < BPB * NHEADS * VNODES; tt += THREADS) {
            int v_ = tt % 10;
            int h  = (tt / 10) & 7;
            int i  = tt / 80;
            const float* qrow = &qs[(i * 10 + v_) * O3 + h * 16];
            float dots[10];
            float m = -1e30f;
            #pragma unroll
            for (int j = 0; j < 10; j++) {
                const float* krow = &qs[(i * 10 + j) * O3 + 128 + h * 16];
                float d = 0.f;
                #pragma unroll
                for (int dd = 0; dd < 16; dd++) d += qrow[dd] * krow[dd];
                d = d * scale * msk[v_ * 10 + j];
                dots[j] = d;
                m = fmaxf(m, d);
            }
            float sum = 0.f;
            #pragma unroll
            for (int j = 0; j < 10; j++) { dots[j] = __expf(dots[j] - m); sum += dots[j]; }
            float inv = 1.0f / sum;
            float o[16];
            #pragma unroll
            for (int dd = 0; dd < 16; dd++) o[dd] = 0.f;
            #pragma unroll
            for (int j = 0; j < 10; j++) {
                float pj = dots[j] * inv;
                const float* vrow = &qs[(i * 10 + j) * O3 + 256 + h * 16];
                #pragma unroll
                for (int dd = 0; dd < 16; dd++) o[dd] += pj * vrow[dd];
            }
            float* ao = &ys[(i * 10 + v_) * CH + h * 16];   // reuse ys as attn output
            #pragma unroll
            for (int dd = 0; dd < 16; dd++) ao[dd] = o[dd];
        }
    }

    // ---- out-proj: out[80][128] = ao[80][128] @ w_out[128][128] + b_out ----
    {
        unsigned long long oa[5][2];
        #pragma unroll
        for (int q = 0; q < 5; q++) { oa[q][0] = 0ull; oa[q][1] = 0ull; }

        for (int kk = 0; kk < 4; kk++) {
            __syncthreads();   // first iter: fences attention ao writes; later: ws reuse
            #pragma unroll
            for (int i = 0; i < (32 * CH) / THREADS; i++) {  // 8 iters
                int idx = tid + i * THREADS;
                ws[idx] = w_out[kk * 32 * CH + idx];
            }
            __syncthreads();

            #pragma unroll 4
            for (int k = 0; k < 32; k++) {
                unsigned long long yv[5];
                #pragma unroll
                for (int q = 0; q < 5; q++) {
                    float v = ys[(rg + 16 * q) * CH + kk * 32 + k];
                    yv[q] = pack2(v, v);
                }
                #pragma unroll
                for (int p = 0; p < 2; p++) {
                    unsigned long long wv =
                        *(const unsigned long long*)&ws[k * CH + 2 * (cp + 32 * p)];
                    #pragma unroll
                    for (int q = 0; q < 5; q++) oa[q][p] = ffma2(yv[q], wv, oa[q][p]);
                }
            }
        }

        float* og = out + row0 * CH;
        #pragma unroll
        for (int q = 0; q < 5; q++) {
            int r = rg + 16 * q;
            #pragma unroll
            for (int p = 0; p < 2; p++) {
                int col = 2 * (cp + 32 * p);
                float lo, hi;
                unpack2(oa[q][p], lo, hi);
                og[r * CH + col]     = lo + bo[col];
                og[r * CH + col + 1] = hi + bo[col + 1];
            }
        }
    }
}

extern "C" void kernel_launch(void* const* d_in, const int* in_sizes, int n_in,
                              void* d_out, int out_size) {
    (void)in_sizes; (void)n_in; (void)out_size;
    const float* x     = (const float*)d_in[0];
    const float* gamma = (const float*)d_in[1];
    const float* beta  = (const float*)d_in[2];
    const float* w_qkv = (const float*)d_in[3];
    const float* w_out = (const float*)d_in[4];
    const float* b_out = (const float*)d_in[5];
    const float* mask  = (const float*)d_in[6];
    float* out = (float*)d_out;

    cudaFuncSetAttribute(fused_kernel, cudaFuncAttributeMaxDynamicSharedMemorySize, SM_BYTES);

    stats_partial<<<STAT_BLOCKS, 128>>>(x);
    stats_final<<<1, 128>>>(gamma, beta);
    fused_kernel<<<BB / BPB, THREADS, SM_BYTES>>>(x, w_qkv, w_out, b_out, mask, out);
}

// round 6
// speedup vs baseline: 1.0122x; 1.0122x over previous
#include <cuda_runtime.h>
#include <cuda_bf16.h>
#include <cstdint>

// ---------------- problem constants ----------------
#define ROWS_TOT  327680            // 32768 graphs * 10 nodes
#define CH        128
#define GR_CTA    12                // graphs per CTA (120 rows -> padded M=128)
#define NCTA      ((32768 + GR_CTA - 1) / GR_CTA)   // 2731

// ---------------- smem layout (bytes) ----------------
#define A_OFF     0                 // Ah 32KB @0, Al 32KB @32768 (bf16, 256B rows, swA). reused: Vbuf fp32 swz512
#define W_OFF     65536             // 32KB slab: hi 16KB, lo 16KB (128B rows, sw128)
#define Q_OFF     98304             // 64KB fp32, 512B rows, swz512 (later holds O fp32)
#define K_OFF     163840            // 64KB fp32 swz512 (later Oh/Ol bf16, swA)
#define AB_OFF    229376            // 256 floats
#define BO_OFF    230400            // 128 floats
#define MSK_OFF   230912            // 128 floats (100 used)
#define SMEM_TOTAL 231424

// ---------------- device globals ----------------
// weight slabs: [tile(3 qkv chunks + wout)][kh(2)] -> 32KB slab = [hi 16KB][lo 16KB]
// inside 16KB: W^T[n(128)][kb(128B = 64 bf16)] with sw128 swizzle
__device__ uint4 g_w[8 * 2048];
__device__ float g_part[512 * 256];
__device__ float g_ab[256];

// ---------------- helpers ----------------
__device__ __forceinline__ uint32_t smem_u32(const void* p) {
    uint32_t a;
    asm("{ .reg .u64 t; cvta.to.shared.u64 t, %1; cvt.u32.u64 %0, t; }" : "=r"(a) : "l"(p));
    return a;
}
__device__ __forceinline__ uint32_t swA(uint32_t off)    { return off ^ ((off >> 4) & 0x70); }  // 256B rows
__device__ __forceinline__ uint32_t sw128(uint32_t off)  { return off ^ ((off >> 3) & 0x70); }  // 128B rows
__device__ __forceinline__ uint32_t swz512(uint32_t off) { return off ^ ((off >> 6) & 0x78); }  // 512B rows, fp32

__device__ __forceinline__ unsigned long long pack2(float lo, float hi) {
    unsigned long long r;
    asm("mov.b64 %0, {%1, %2};" : "=l"(r) : "f"(lo), "f"(hi));
    return r;
}
__device__ __forceinline__ void unpack2(unsigned long long v, float& lo, float& hi) {
    asm("mov.b64 {%0, %1}, %2;" : "=f"(lo), "=f"(hi) : "l"(v));
}
__device__ __forceinline__ unsigned long long ffma2(unsigned long long a,
                                                    unsigned long long b,
                                                    unsigned long long c) {
    unsigned long long d;
    asm("fma.rn.f32x2 %0, %1, %2, %3;" : "=l"(d) : "l"(a), "l"(b), "l"(c));
    return d;
}

#define LDSM4(r, addr)                                                        \
    asm volatile("ldmatrix.sync.aligned.m8n8.x4.shared.b16 {%0,%1,%2,%3}, [%4];" \
                 : "=r"((r)[0]), "=r"((r)[1]), "=r"((r)[2]), "=r"((r)[3])     \
                 : "r"(addr))

#define MMA(d, a, b0v, b1v)                                                   \
    asm volatile("mma.sync.aligned.m16n8k16.row.col.f32.bf16.bf16.f32 "       \
                 "{%0,%1,%2,%3},{%4,%5,%6,%7},{%8,%9},{%0,%1,%2,%3};"         \
                 : "+f"((d)[0]), "+f"((d)[1]), "+f"((d)[2]), "+f"((d)[3])     \
                 : "r"((a)[0]), "r"((a)[1]), "r"((a)[2]), "r"((a)[3]),        \
                   "r"(b0v), "r"(b1v))

// ---------------- K0: split + swizzle weights ----------------
__global__ void __launch_bounds__(256) prep_weights(const float* __restrict__ w_qkv,
                                                    const float* __restrict__ w_out) {
    int idx = blockIdx.x * 256 + threadIdx.x;          // 0..65535
    int tile = idx >> 14, rem = idx & 16383;
    int n = rem >> 7, k = rem & 127;
    float v = (tile < 3) ? w_qkv[k * 384 + tile * 128 + n] : w_out[k * 128 + n];
    __nv_bfloat16 h = __float2bfloat16(v);
    __nv_bfloat16 l = __float2bfloat16(v - __bfloat162float(h));
    int kh = k >> 6;
    uint32_t off = sw128((uint32_t)n * 128 + (uint32_t)(k & 63) * 2);
    char* slab = (char*)g_w + (tile * 2 + kh) * 32768;
    *(__nv_bfloat16*)(slab + off)         = h;
    *(__nv_bfloat16*)(slab + 16384 + off) = l;
}

// ---------------- K1: partial BN stats ----------------
__global__ void __launch_bounds__(256) stats1(const float* __restrict__ x) {
    __shared__ float red[2048];
    int tid = threadIdx.x, c4 = tid & 31, rg = tid >> 5;
    size_t r0 = (size_t)blockIdx.x * 640;
    const float4* p = (const float4*)(x + r0 * CH) + c4;
    float sx = 0, sy = 0, sz = 0, sw = 0, qx = 0, qy = 0, qz = 0, qw = 0;
    #pragma unroll 8
    for (int r = rg; r < 640; r += 8) {
        float4 v = p[(size_t)r * 32];
        sx += v.x; sy += v.y; sz += v.z; sw += v.w;
        qx += v.x * v.x; qy += v.y * v.y; qz += v.z * v.z; qw += v.w * v.w;
    }
    float* rr = red + tid * 8;
    rr[0] = sx; rr[1] = sy; rr[2] = sz; rr[3] = sw;
    rr[4] = qx; rr[5] = qy; rr[6] = qz; rr[7] = qw;
    __syncthreads();
    if (tid < 32) {
        float s[8] = {0, 0, 0, 0, 0, 0, 0, 0};
        for (int g = 0; g < 8; g++) {
            const float* r2 = red + (g * 32 + tid) * 8;
            #pragma unroll
            for (int i = 0; i < 8; i++) s[i] += r2[i];
        }
        #pragma unroll
        for (int i = 0; i < 4; i++) {
            g_part[blockIdx.x * 256 + tid * 4 + i]       = s[i];
            g_part[blockIdx.x * 256 + 128 + tid * 4 + i] = s[4 + i];
        }
    }
}

// ---------------- K2: finalize ----------------
__global__ void __launch_bounds__(256) stats2(const float* __restrict__ gamma,
                                              const float* __restrict__ beta) {
    __shared__ float sred[256];
    int tid = threadIdx.x, half = tid >> 7, c = tid & 127;
    float acc = 0.f;
    #pragma unroll 8
    for (int b = 0; b < 512; b++) acc += g_part[b * 256 + half * 128 + c];
    sred[tid] = acc;
    __syncthreads();
    if (tid < 128) {
        const float invN = 1.0f / (float)ROWS_TOT;
        float mean = sred[tid] * invN;
        float var  = sred[128 + tid] * invN - mean * mean;
        float a = gamma[tid] * rsqrtf(var + 1e-5f);
        g_ab[tid]       = a;
        g_ab[128 + tid] = beta[tid] - mean * a;
    }
}

// ---------------- GEMM tile body: 4 k16-steps ----------------
__device__ __forceinline__ void gemm_ksteps(uint32_t aHi, uint32_t aLo,
                                            uint32_t wHi, uint32_t wLo,
                                            int kbase, int mg, int ng, int lane,
                                            float acc[4][4][4]) {
    const int rowA  = mg * 64 + (lane & 15);
    const int rowN  = ng * 32 + (lane & 15);
    const int khalf = (lane >> 4) << 4;   // 0 or 16 bytes
    #pragma unroll
    for (int ks = 0; ks < 4; ks++) {
        uint32_t ah[4][4], al[4][4], bh[2][4], bl[2][4];
        uint32_t kbA = (uint32_t)(kbase + ks * 16) * 2 + khalf;
        #pragma unroll
        for (int mt = 0; mt < 4; mt++) {
            uint32_t off = swA((uint32_t)(rowA + mt * 16) * 256 + kbA);
            LDSM4(ah[mt], aHi + off);
            LDSM4(al[mt], aLo + off);
        }
        uint32_t kbW = (uint32_t)(ks * 32) + khalf;
        #pragma unroll
        for (int xi = 0; xi < 2; xi++) {
            uint32_t off = sw128((uint32_t)(rowN + xi * 16) * 128 + kbW);
            LDSM4(bh[xi], wHi + off);
            LDSM4(bl[xi], wLo + off);
        }
        #pragma unroll
        for (int mt = 0; mt < 4; mt++)
            #pragma unroll
            for (int xi = 0; xi < 2; xi++)
                #pragma unroll
                for (int hf = 0; hf < 2; hf++) {
                    float* d = acc[mt][xi * 2 + hf];
                    MMA(d, ah[mt], bh[xi][hf], bh[xi][hf + 2]);
                    MMA(d, ah[mt], bl[xi][hf], bl[xi][hf + 2]);
                    MMA(d, al[mt], bh[xi][hf], bh[xi][hf + 2]);
                }
    }
}

// store accumulators (fp32) into swz512 region + zero them
__device__ __forceinline__ void store_d(char* smc, uint32_t roff,
                                        int mg, int ng, int lane, float acc[4][4][4]) {
    #pragma unroll
    for (int mt = 0; mt < 4; mt++)
        #pragma unroll
        for (int nt = 0; nt < 4; nt++) {
            int r   = mg * 64 + mt * 16 + (lane >> 2);
            int col = ng * 32 + nt * 8 + 2 * (lane & 3);
            float* a = acc[mt][nt];
            *(float2*)(smc + roff + swz512((uint32_t)r * 512 + (uint32_t)col * 4)) =
                make_float2(a[0], a[1]);
            *(float2*)(smc + roff + swz512((uint32_t)(r + 8) * 512 + (uint32_t)col * 4)) =
                make_float2(a[2], a[3]);
            a[0] = a[1] = a[2] = a[3] = 0.f;
        }
}

// ---------------- K3: fused pipeline ----------------
__global__ void __launch_bounds__(256, 1) fused(const float* __restrict__ x,
                                                const float* __restrict__ mask,
                                                const float* __restrict__ b_out,
                                                float* __restrict__ out) {
    extern __shared__ char smc[];
    const uint32_t sb = smem_u32(smc);
    const int tid = threadIdx.x, wid = tid >> 5, lane = tid & 31;
    const int mg = wid >> 2, ng = wid & 3;

    float* abf  = (float*)(smc + AB_OFF);
    float* bof  = (float*)(smc + BO_OFF);
    float* mskf = (float*)(smc + MSK_OFF);

    // prefetch weight slab 0
    uint4 pf[8];
    #pragma unroll
    for (int i = 0; i < 8; i++) pf[i] = g_w[tid + i * 256];

    abf[tid] = g_ab[tid];
    if (tid < 128) bof[tid] = b_out[tid];
    if (tid < 100) mskf[tid] = mask[tid];
    __syncthreads();

    const size_t grow0 = (size_t)blockIdx.x * 120;

    // ---- phase 1: x -> BN -> bf16 hi/lo A tiles ----
    {
        #pragma unroll 4
        for (int i = 0; i < 32; i++) {
            int idx = tid + i * 256;           // (p 0..127, cp 0..63)
            int p = idx >> 6, cp = idx & 63;
            size_t real = grow0 + p;
            float2 v = make_float2(0.f, 0.f);
            if (p < 120 && real < ROWS_TOT)
                v = ((const float2*)(x + real * CH))[cp];
            int c = cp * 2;
            float y0 = v.x * abf[c]     + abf[128 + c];
            float y1 = v.y * abf[c + 1] + abf[129 + c];
            __nv_bfloat16 h0 = __float2bfloat16(y0);
            __nv_bfloat16 h1 = __float2bfloat16(y1);
            __nv_bfloat16 l0 = __float2bfloat16(y0 - __bfloat162float(h0));
            __nv_bfloat16 l1 = __float2bfloat16(y1 - __bfloat162float(h1));
            uint32_t off = swA((uint32_t)p * 256 + (uint32_t)c * 2);
            *(__nv_bfloat162*)(smc + A_OFF + off)         = __nv_bfloat162(h0, h1);
            *(__nv_bfloat162*)(smc + A_OFF + 32768 + off) = __nv_bfloat162(l0, l1);
        }
    }

    float acc[4][4][4];
    #pragma unroll
    for (int a1 = 0; a1 < 4; a1++)
        #pragma unroll
        for (int a2 = 0; a2 < 4; a2++)
            #pragma unroll
            for (int a3 = 0; a3 < 4; a3++) acc[a1][a2][a3] = 0.f;

    uint4* ws = (uint4*)(smc + W_OFF);
    const uint32_t aHi = sb + A_OFF, aLo = sb + A_OFF + 32768;
    const uint32_t wHi = sb + W_OFF, wLo = sb + W_OFF + 16384;

    // ---- phase 2: GEMM1 (QKV), slabs 0..5 ----
    for (int s = 0; s < 6; s++) {
        __syncthreads();
        #pragma unroll
        for (int i = 0; i < 8; i++) ws[tid + i * 256] = pf[i];
        #pragma unroll
        for (int i = 0; i < 8; i++) pf[i] = g_w[(s + 1) * 2048 + tid + i * 256];
        __syncthreads();
        gemm_ksteps(aHi, aLo, wHi, wLo, (s & 1) * 64, mg, ng, lane, acc);
        if (s == 1)      store_d(smc, Q_OFF, mg, ng, lane, acc);
        else if (s == 3) store_d(smc, K_OFF, mg, ng, lane, acc);
    }
    __syncthreads();                       // all A readers done
    store_d(smc, A_OFF, mg, ng, lane, acc);  // V -> A region (fp32 swz512)
    // stage w_out kh0 slab, prefetch kh1
    #pragma unroll
    for (int i = 0; i < 8; i++) ws[tid + i * 256] = pf[i];
    #pragma unroll
    for (int i = 0; i < 8; i++) pf[i] = g_w[7 * 2048 + tid + i * 256];
    __syncthreads();                       // V + Wbuf(slab6) ready

    // ---- phase 3: attention (240 tasks: row x head-half) ----
    if (tid < 240) {
        const int r = tid >> 1, hh = tid & 1;
        const int g = r / 10, vloc = r - g * 10;
        const int jb = g * 10;
        #pragma unroll
        for (int hi2 = 0; hi2 < 4; hi2++) {
            const int h = hh * 4 + hi2;
            const uint32_t hb = (uint32_t)h * 64;   // byte offset of head slice
            unsigned long long q[8];
            #pragma unroll
            for (int d = 0; d < 8; d++)
                q[d] = *(const unsigned long long*)(smc + Q_OFF +
                        swz512((uint32_t)r * 512 + hb + d * 8));
            float dots[10], mx = -1e30f;
            #pragma unroll
            for (int j = 0; j < 10; j++) {
                unsigned long long s2 = 0ull;
                uint32_t kr = (uint32_t)(jb + j) * 512 + hb;
                #pragma unroll
                for (int d = 0; d < 8; d++)
                    s2 = ffma2(q[d],
                               *(const unsigned long long*)(smc + K_OFF + swz512(kr + d * 8)),
                               s2);
                float lo, hi;
                unpack2(s2, lo, hi);
                float dd = (lo + hi) * 0.25f * mskf[vloc * 10 + j];
                dots[j] = dd;
                mx = fmaxf(mx, dd);
            }
            float sum = 0.f;
            #pragma unroll
            for (int j = 0; j < 10; j++) { dots[j] = __expf(dots[j] - mx); sum += dots[j]; }
            float inv = 1.0f / sum;
            unsigned long long o8[8];
            #pragma unroll
            for (int d = 0; d < 8; d++) o8[d] = 0ull;
            #pragma unroll
            for (int j = 0; j < 10; j++) {
                unsigned long long pj = pack2(dots[j] * inv, dots[j] * inv);
                uint32_t vr = (uint32_t)(jb + j) * 512 + hb;
                #pragma unroll
                for (int d = 0; d < 8; d++)
                    o8[d] = ffma2(pj,
                                  *(const unsigned long long*)(smc + A_OFF + swz512(vr + d * 8)),
                                  o8[d]);
            }
            #pragma unroll
            for (int d = 0; d < 8; d++)
                *(unsigned long long*)(smc + Q_OFF + swz512((uint32_t)r * 512 + hb + d * 8)) = o8[d];
        }
    }
    __syncthreads();

    // ---- phase 4: convert O fp32 -> bf16 hi/lo into K region ----
    {
        const int r = tid >> 1, half = tid & 1;
        #pragma unroll 4
        for (int i = 0; i < 32; i++) {
            int col = half * 64 + i * 2;
            float2 v = *(const float2*)(smc + Q_OFF +
                        swz512((uint32_t)r * 512 + (uint32_t)col * 4));
            __nv_bfloat16 h0 = __float2bfloat16(v.x);
            __nv_bfloat16 h1 = __float2bfloat16(v.y);
            __nv_bfloat16 l0 = __float2bfloat16(v.x - __bfloat162float(h0));
            __nv_bfloat16 l1 = __float2bfloat16(v.y - __bfloat162float(h1));
            uint32_t off = swA((uint32_t)r * 256 + (uint32_t)col * 2);
            *(__nv_bfloat162*)(smc + K_OFF + off)         = __nv_bfloat162(h0, h1);
            *(__nv_bfloat162*)(smc + K_OFF + 32768 + off) = __nv_bfloat162(l0, l1);
        }
    }
    __syncthreads();

    // ---- phase 5: GEMM2 (out-proj) ----
    const uint32_t oHi = sb + K_OFF, oLo = sb + K_OFF + 32768;
    gemm_ksteps(oHi, oLo, wHi, wLo, 0, mg, ng, lane, acc);
    __syncthreads();
    #pragma unroll
    for (int i = 0; i < 8; i++) ws[tid + i * 256] = pf[i];
    __syncthreads();
    gemm_ksteps(oHi, oLo, wHi, wLo, 64, mg, ng, lane, acc);

    // ---- phase 6: epilogue (bias + direct global store) ----
    #pragma unroll
    for (int mt = 0; mt < 4; mt++)
        #pragma unroll
        for (int nt = 0; nt < 4; nt++) {
            int r0 = mg * 64 + mt * 16 + (lane >> 2);
            int col = ng * 32 + nt * 8 + 2 * (lane & 3);
            float b0v = bof[col], b1v = bof[col + 1];
            float* a = acc[mt][nt];
            #pragma unroll
            for (int hf = 0; hf < 2; hf++) {
                int r = r0 + hf * 8;
                size_t real = grow0 + r;
                if (r < 120 && real < ROWS_TOT)
                    *(float2*)(out + real * CH + col) =
                        make_float2(a[2 * hf] + b0v, a[2 * hf + 1] + b1v);
            }
        }
}

// ---------------- launch ----------------
extern "C" void kernel_launch(void* const* d_in, const int* in_sizes, int n_in,
                              void* d_out, int out_size) {
    (void)in_sizes; (void)n_in; (void)out_size;
    const float* x     = (const float*)d_in[0];
    const float* gamma = (const float*)d_in[1];
    const float* beta  = (const float*)d_in[2];
    const float* w_qkv = (const float*)d_in[3];
    const float* w_out = (const float*)d_in[4];
    const float* b_out = (const float*)d_in[5];
    const float* mask  = (const float*)d_in[6];
    float* out = (float*)d_out;

    cudaFuncSetAttribute(fused, cudaFuncAttributeMaxDynamicSharedMemorySize, SMEM_TOTAL);

    prep_weights<<<256, 256>>>(w_qkv, w_out);
    stats1<<<512, 256>>>(x);
    stats2<<<1, 256>>>(gamma, beta);
    fused<<<NCTA, 256, SMEM_TOTAL>>>(x, mask, b_out, out);
}

// round 8
// speedup vs baseline: 3.0567x; 3.0197x over previous
#include <cuda_runtime.h>
#include <cuda_fp16.h>
#include <cstdint>

// ---------------- problem constants ----------------
#define ROWS_TOT  327680            // 32768 graphs * 10 nodes
#define CH        128
#define GR_CTA    6                 // graphs per CTA (60 rows -> padded M=64)
#define NCTA      ((32768 + GR_CTA - 1) / GR_CTA)   // 5462

// ---------------- smem layout (bytes) ----------------
#define A_OFF     0                 // 16KB fp16 swA: A (BN input), later O
#define W_OFF     16384             // 32KB weight slab [n128][k128 fp16], swA
#define QKV_OFF   49152             // 3 bufs, 64 rows x 260B stride
#define QBUF_B    16640
#define AB_OFF    99072             // 256 floats
#define BO_OFF    100096            // 128 floats
#define MSK_OFF   100608            // 100 floats
#define SMEM_TOTAL 101120

// ---------------- device globals ----------------
// 4 weight tiles (Qc,Kc,Vc,Wout): [n128][k128] fp16, 256B rows, swA swizzle
__device__ uint4 g_w[4 * 2048];
__device__ float g_part[1024 * 256];
__device__ float g_ab[256];

// ---------------- helpers ----------------
__device__ __forceinline__ uint32_t smem_u32(const void* p) {
    uint32_t a;
    asm("{ .reg .u64 t; cvta.to.shared.u64 t, %1; cvt.u32.u64 %0, t; }" : "=r"(a) : "l"(p));
    return a;
}
// swizzle for 256B rows: XOR 16B-chunk bits [6:4] with row bits [10:8]
__device__ __forceinline__ uint32_t swA(uint32_t off) { return off ^ ((off >> 4) & 0x70); }

#define LDSM4(r, addr)                                                        \
    asm volatile("ldmatrix.sync.aligned.m8n8.x4.shared.b16 {%0,%1,%2,%3}, [%4];" \
                 : "=r"((r)[0]), "=r"((r)[1]), "=r"((r)[2]), "=r"((r)[3])     \
                 : "r"(addr))

#define MMA(d, a, b0v, b1v)                                                   \
    asm volatile("mma.sync.aligned.m16n8k16.row.col.f32.f16.f16.f32 "         \
                 "{%0,%1,%2,%3},{%4,%5,%6,%7},{%8,%9},{%0,%1,%2,%3};"         \
                 : "+f"((d)[0]), "+f"((d)[1]), "+f"((d)[2]), "+f"((d)[3])     \
                 : "r"((a)[0]), "r"((a)[1]), "r"((a)[2]), "r"((a)[3]),        \
                   "r"(b0v), "r"(b1v))

// ---------------- K0: fp16 + swizzle weights ----------------
__global__ void __launch_bounds__(256) prep_weights(const float* __restrict__ w_qkv,
                                                    const float* __restrict__ w_out) {
    int idx = blockIdx.x * 256 + threadIdx.x;          // 0..65535
    int tile = idx >> 14, rem = idx & 16383;
    int n = rem >> 7, k = rem & 127;
    float v = (tile < 3) ? w_qkv[k * 384 + tile * 128 + n] : w_out[k * 128 + n];
    char* slab = (char*)g_w + tile * 32768;
    *(__half*)(slab + swA((uint32_t)n * 256 + (uint32_t)k * 2)) = __float2half_rn(v);
}

// ---------------- K1: partial BN stats ----------------
__global__ void __launch_bounds__(256) stats1(const float* __restrict__ x) {
    __shared__ float red[2048];
    int tid = threadIdx.x, c4 = tid & 31, rg = tid >> 5;
    size_t r0 = (size_t)blockIdx.x * 320;
    const float4* p = (const float4*)(x + r0 * CH) + c4;
    float sx = 0, sy = 0, sz = 0, sw = 0, qx = 0, qy = 0, qz = 0, qw = 0;
    #pragma unroll 8
    for (int r = rg; r < 320; r += 8) {
        float4 v = p[(size_t)r * 32];
        sx += v.x; sy += v.y; sz += v.z; sw += v.w;
        qx += v.x * v.x; qy += v.y * v.y; qz += v.z * v.z; qw += v.w * v.w;
    }
    float* rr = red + tid * 8;
    rr[0] = sx; rr[1] = sy; rr[2] = sz; rr[3] = sw;
    rr[4] = qx; rr[5] = qy; rr[6] = qz; rr[7] = qw;
    __syncthreads();
    if (tid < 32) {
        float s[8] = {0, 0, 0, 0, 0, 0, 0, 0};
        for (int g = 0; g < 8; g++) {
            const float* r2 = red + (g * 32 + tid) * 8;
            #pragma unroll
            for (int i = 0; i < 8; i++) s[i] += r2[i];
        }
        #pragma unroll
        for (int i = 0; i < 4; i++) {
            g_part[blockIdx.x * 256 + tid * 4 + i]       = s[i];
            g_part[blockIdx.x * 256 + 128 + tid * 4 + i] = s[4 + i];
        }
    }
}

// ---------------- K2: finalize ----------------
__global__ void __launch_bounds__(256) stats2(const float* __restrict__ gamma,
                                              const float* __restrict__ beta) {
    __shared__ float sred[256];
    int tid = threadIdx.x, half = tid >> 7, c = tid & 127;
    float acc = 0.f;
    #pragma unroll 8
    for (int b = 0; b < 1024; b++) acc += g_part[b * 256 + half * 128 + c];
    sred[tid] = acc;
    __syncthreads();
    if (tid < 128) {
        const float invN = 1.0f / (float)ROWS_TOT;
        float mean = sred[tid] * invN;
        float var  = sred[128 + tid] * invN - mean * mean;
        float a = gamma[tid] * rsqrtf(var + 1e-5f);
        g_ab[tid]       = a;
        g_ab[128 + tid] = beta[tid] - mean * a;
    }
}

// ---------------- GEMM m64 x n128 x k128, single fp16 ----------------
__device__ __forceinline__ void gemm128(uint32_t aBase, uint32_t wBase,
                                        int mg, int ng, int lane, float acc[2][4][4]) {
    const int rowA  = mg * 32 + (lane & 15);
    const int rowN  = ng * 32 + (lane & 15);
    const uint32_t khalf = ((uint32_t)lane >> 4) * 16;
    #pragma unroll
    for (int ks = 0; ks < 8; ks++) {
        uint32_t a_[2][4], b_[2][4];
        uint32_t kb = (uint32_t)ks * 32 + khalf;
        #pragma unroll
        for (int mt = 0; mt < 2; mt++)
            LDSM4(a_[mt], aBase + swA((uint32_t)(rowA + mt * 16) * 256 + kb));
        #pragma unroll
        for (int xi = 0; xi < 2; xi++)
            LDSM4(b_[xi], wBase + swA((uint32_t)(rowN + xi * 16) * 256 + kb));
        #pragma unroll
        for (int mt = 0; mt < 2; mt++)
            #pragma unroll
            for (int xi = 0; xi < 2; xi++)
                #pragma unroll
                for (int hf = 0; hf < 2; hf++)
                    MMA(acc[mt][xi * 2 + hf], a_[mt], b_[xi][hf], b_[xi][hf + 2]);
    }
}

// accumulators -> fp16 buffer (260B row stride), then zero
__device__ __forceinline__ void acc_to_buf(char* smc, uint32_t boff,
                                           int mg, int ng, int lane, float acc[2][4][4]) {
    #pragma unroll
    for (int mt = 0; mt < 2; mt++)
        #pragma unroll
        for (int nt = 0; nt < 4; nt++) {
            int r   = mg * 32 + mt * 16 + (lane >> 2);
            int col = ng * 32 + nt * 8 + 2 * (lane & 3);
            float* a = acc[mt][nt];
            *(__half2*)(smc + boff + (uint32_t)r * 260 + (uint32_t)col * 2) =
                __floats2half2_rn(a[0], a[1]);
            *(__half2*)(smc + boff + (uint32_t)(r + 8) * 260 + (uint32_t)col * 2) =
                __floats2half2_rn(a[2], a[3]);
            a[0] = a[1] = a[2] = a[3] = 0.f;
        }
}

// ---------------- K3: fused pipeline ----------------
__global__ void __launch_bounds__(256, 2) fused(const float* __restrict__ x,
                                                const float* __restrict__ mask,
                                                const float* __restrict__ b_out,
                                                float* __restrict__ out) {
    extern __shared__ char smc[];
    const uint32_t sb = smem_u32(smc);
    const int tid = threadIdx.x, wid = tid >> 5, lane = tid & 31;
    const int mg = wid >> 2, ng = wid & 3;

    float* abf  = (float*)(smc + AB_OFF);
    float* bof  = (float*)(smc + BO_OFF);
    float* mskf = (float*)(smc + MSK_OFF);

    // prefetch weight slab 0 (Q chunk)
    uint4 pf[8];
    #pragma unroll
    for (int i = 0; i < 8; i++) pf[i] = g_w[tid + i * 256];

    abf[tid] = g_ab[tid];
    if (tid < 128) bof[tid] = b_out[tid];
    if (tid < 100) mskf[tid] = mask[tid];
    __syncthreads();

    const size_t grow0 = (size_t)blockIdx.x * 60;

    // ---- phase 1: x -> BN -> fp16 A tile (64 rows) ----
    #pragma unroll 4
    for (int i = 0; i < 16; i++) {
        int idx = tid + i * 256;            // p 0..63, cp 0..63
        int p = idx >> 6, cp = idx & 63;
        size_t real = grow0 + p;
        float2 v = make_float2(0.f, 0.f);
        if (p < 60 && real < ROWS_TOT)
            v = ((const float2*)(x + real * CH))[cp];
        int c = cp * 2;
        float y0 = v.x * abf[c]     + abf[128 + c];
        float y1 = v.y * abf[c + 1] + abf[129 + c];
        *(__half2*)(smc + A_OFF + swA((uint32_t)p * 256 + (uint32_t)cp * 4)) =
            __floats2half2_rn(y0, y1);
    }

    float acc[2][4][4];
    #pragma unroll
    for (int a1 = 0; a1 < 2; a1++)
        #pragma unroll
        for (int a2 = 0; a2 < 4; a2++)
            #pragma unroll
            for (int a3 = 0; a3 < 4; a3++) acc[a1][a2][a3] = 0.f;

    uint4* ws = (uint4*)(smc + W_OFF);
    const uint32_t aBase = sb + A_OFF, wBase = sb + W_OFF;

    // ---- phase 2: GEMM1 (Q,K,V chunks) ----
    for (int s = 0; s < 3; s++) {
        __syncthreads();
        #pragma unroll
        for (int i = 0; i < 8; i++) ws[tid + i * 256] = pf[i];
        #pragma unroll
        for (int i = 0; i < 8; i++) pf[i] = g_w[(s + 1) * 2048 + tid + i * 256];
        __syncthreads();
        gemm128(aBase, wBase, mg, ng, lane, acc);
        acc_to_buf(smc, QKV_OFF + s * QBUF_B, mg, ng, lane, acc);
    }
    __syncthreads();   // QKV bufs complete, A region free

    // ---- phase 3: attention, 512 padded tasks (r 0..63, h 0..7) ----
    #pragma unroll
    for (int it = 0; it < 2; it++) {
        int t = tid + it * 256;
        int h = t >> 6, r = t & 63;
        size_t realr = grow0 + r;
        if (r < 60 && realr < ROWS_TOT) {
            int g = r / 10, vloc = r - g * 10;
            uint32_t hb = (uint32_t)h * 32;           // head byte offset in row
            const char* Qb = smc + QKV_OFF;
            const char* Kb = smc + QKV_OFF + QBUF_B;
            const char* Vb = smc + QKV_OFF + 2 * QBUF_B;
            float2 qf[8];
            #pragma unroll
            for (int d = 0; d < 8; d++)
                qf[d] = __half22float2(*(const __half2*)(Qb + (uint32_t)r * 260 + hb + d * 4));
            float dots[10], mx = -1e30f;
            #pragma unroll
            for (int j = 0; j < 10; j++) {
                const char* kr = Kb + (uint32_t)(g * 10 + j) * 260 + hb;
                float dd = 0.f;
                #pragma unroll
                for (int d = 0; d < 8; d++) {
                    float2 kf = __half22float2(*(const __half2*)(kr + d * 4));
                    dd += qf[d].x * kf.x + qf[d].y * kf.y;
                }
                dd = dd * 0.25f * mskf[vloc * 10 + j];
                dots[j] = dd;
                mx = fmaxf(mx, dd);
            }
            float sum = 0.f;
            #pragma unroll
            for (int j = 0; j < 10; j++) { dots[j] = __expf(dots[j] - mx); sum += dots[j]; }
            float inv = 1.0f / sum;
            float o[16];
            #pragma unroll
            for (int d = 0; d < 16; d++) o[d] = 0.f;
            #pragma unroll
            for (int j = 0; j < 10; j++) {
                float pj = dots[j] * inv;
                const char* vr = Vb + (uint32_t)(g * 10 + j) * 260 + hb;
                #pragma unroll
                for (int d = 0; d < 8; d++) {
                    float2 vf = __half22float2(*(const __half2*)(vr + d * 4));
                    o[2 * d]     += pj * vf.x;
                    o[2 * d + 1] += pj * vf.y;
                }
            }
            // O -> A region (fp16, swA layout) as GEMM2 input
            #pragma unroll
            for (int d = 0; d < 8; d++)
                *(__half2*)(smc + A_OFF + swA((uint32_t)r * 256 + hb + d * 4)) =
                    __floats2half2_rn(o[2 * d], o[2 * d + 1]);
        }
    }
    __syncthreads();

    // ---- phase 4: GEMM2 (out-proj) ----
    #pragma unroll
    for (int i = 0; i < 8; i++) ws[tid + i * 256] = pf[i];
    __syncthreads();
    gemm128(aBase, wBase, mg, ng, lane, acc);

    // ---- phase 5: epilogue (bias + global store) ----
    #pragma unroll
    for (int mt = 0; mt < 2; mt++)
        #pragma unroll
        for (int nt = 0; nt < 4; nt++) {
            int r0 = mg * 32 + mt * 16 + (lane >> 2);
            int col = ng * 32 + nt * 8 + 2 * (lane & 3);
            float b0v = bof[col], b1v = bof[col + 1];
            float* a = acc[mt][nt];
            #pragma unroll
            for (int hf = 0; hf < 2; hf++) {
                int r = r0 + hf * 8;
                size_t real = grow0 + r;
                if (r < 60 && real < ROWS_TOT)
                    *(float2*)(out + real * CH + col) =
                        make_float2(a[2 * hf] + b0v, a[2 * hf + 1] + b1v);
            }
        }
}

// ---------------- launch ----------------
extern "C" void kernel_launch(void* const* d_in, const int* in_sizes, int n_in,
                              void* d_out, int out_size) {
    (void)in_sizes; (void)n_in; (void)out_size;
    const float* x     = (const float*)d_in[0];
    const float* gamma = (const float*)d_in[1];
    const float* beta  = (const float*)d_in[2];
    const float* w_qkv = (const float*)d_in[3];
    const float* w_out = (const float*)d_in[4];
    const float* b_out = (const float*)d_in[5];
    const float* mask  = (const float*)d_in[6];
    float* out = (float*)d_out;

    cudaFuncSetAttribute(fused, cudaFuncAttributeMaxDynamicSharedMemorySize, SMEM_TOTAL);

    prep_weights<<<256, 256>>>(w_qkv, w_out);
    stats1<<<1024, 256>>>(x);
    stats2<<<1, 256>>>(gamma, beta);
    fused<<<NCTA, 256, SMEM_TOTAL>>>(x, mask, b_out, out);
}

// round 9
// speedup vs baseline: 3.4072x; 1.1147x over previous
#include <cuda_runtime.h>
#include <cuda_fp16.h>
#include <cstdint>

// ---------------- problem constants ----------------
#define ROWS_TOT  327680            // 32768 graphs * 10 nodes
#define CH        128
#define GR_CTA    6                 // graphs per CTA (60 rows -> padded M=64)
#define NCTA      ((32768 + GR_CTA - 1) / GR_CTA)   // 5462

// ---------------- smem layout (bytes) ----------------
#define A_OFF     0                 // 16KB fp16 swA: A (BN input), later O
#define W_OFF     16384             // 32KB weight slab [n128][k128 fp16], swA
#define QKV_OFF   49152             // 3 bufs, 64 rows x 272B stride (16B aligned)
#define QBUF_B    17408             // 64*272
#define AB_OFF    101376            // 256 floats
#define BO_OFF    102400            // 128 floats
#define MSK_OFF   102912            // 100 floats
#define SMEM_TOTAL 103424

#define STAT_BLOCKS 2048
#define ROWS_PER_STAT (ROWS_TOT / STAT_BLOCKS)   // 160

// ---------------- device globals ----------------
__device__ uint4 g_w[4 * 2048];           // 4 tiles [n128][k128] fp16, swA
__device__ float g_part[STAT_BLOCKS * 256];
__device__ float g_ab[256];

// ---------------- helpers ----------------
__device__ __forceinline__ uint32_t smem_u32(const void* p) {
    uint32_t a;
    asm("{ .reg .u64 t; cvta.to.shared.u64 t, %1; cvt.u32.u64 %0, t; }" : "=r"(a) : "l"(p));
    return a;
}
__device__ __forceinline__ uint32_t swA(uint32_t off) { return off ^ ((off >> 4) & 0x70); }

__device__ __forceinline__ void ld8f(const char* p, float2* f) {
    uint4 u = *(const uint4*)p;
    f[0] = __half22float2(*(__half2*)&u.x);
    f[1] = __half22float2(*(__half2*)&u.y);
    f[2] = __half22float2(*(__half2*)&u.z);
    f[3] = __half22float2(*(__half2*)&u.w);
}

#define LDSM4(r, addr)                                                        \
    asm volatile("ldmatrix.sync.aligned.m8n8.x4.shared.b16 {%0,%1,%2,%3}, [%4];" \
                 : "=r"((r)[0]), "=r"((r)[1]), "=r"((r)[2]), "=r"((r)[3])     \
                 : "r"(addr))

#define MMA(d, a, b0v, b1v)                                                   \
    asm volatile("mma.sync.aligned.m16n8k16.row.col.f32.f16.f16.f32 "         \
                 "{%0,%1,%2,%3},{%4,%5,%6,%7},{%8,%9},{%0,%1,%2,%3};"         \
                 : "+f"((d)[0]), "+f"((d)[1]), "+f"((d)[2]), "+f"((d)[3])     \
                 : "r"((a)[0]), "r"((a)[1]), "r"((a)[2]), "r"((a)[3]),        \
                   "r"(b0v), "r"(b1v))

// ---------------- K0: fp16 + swizzle weights ----------------
__global__ void __launch_bounds__(256) prep_weights(const float* __restrict__ w_qkv,
                                                    const float* __restrict__ w_out) {
    int idx = blockIdx.x * 256 + threadIdx.x;          // 0..65535
    int tile = idx >> 14, rem = idx & 16383;
    int n = rem >> 7, k = rem & 127;
    float v = (tile < 3) ? w_qkv[k * 384 + tile * 128 + n] : w_out[k * 128 + n];
    char* slab = (char*)g_w + tile * 32768;
    *(__half*)(slab + swA((uint32_t)n * 256 + (uint32_t)k * 2)) = __float2half_rn(v);
}

// ---------------- K1: partial BN stats ----------------
__global__ void __launch_bounds__(256) stats1(const float* __restrict__ x) {
    __shared__ float red[2048];
    int tid = threadIdx.x, c4 = tid & 31, rg = tid >> 5;
    size_t r0 = (size_t)blockIdx.x * ROWS_PER_STAT;
    const float4* p = (const float4*)(x + r0 * CH) + c4;
    float sx = 0, sy = 0, sz = 0, sw = 0, qx = 0, qy = 0, qz = 0, qw = 0;
    #pragma unroll 10
    for (int r = rg; r < ROWS_PER_STAT; r += 8) {
        float4 v = p[(size_t)r * 32];
        sx += v.x; sy += v.y; sz += v.z; sw += v.w;
        qx += v.x * v.x; qy += v.y * v.y; qz += v.z * v.z; qw += v.w * v.w;
    }
    float* rr = red + tid * 8;
    rr[0] = sx; rr[1] = sy; rr[2] = sz; rr[3] = sw;
    rr[4] = qx; rr[5] = qy; rr[6] = qz; rr[7] = qw;
    __syncthreads();
    if (tid < 32) {
        float s[8] = {0, 0, 0, 0, 0, 0, 0, 0};
        for (int g = 0; g < 8; g++) {
            const float* r2 = red + (g * 32 + tid) * 8;
            #pragma unroll
            for (int i = 0; i < 8; i++) s[i] += r2[i];
        }
        #pragma unroll
        for (int i = 0; i < 4; i++) {
            g_part[blockIdx.x * 256 + tid * 4 + i]       = s[i];
            g_part[blockIdx.x * 256 + 128 + tid * 4 + i] = s[4 + i];
        }
    }
}

// ---------------- K2: finalize (1024-thread parallel reduce) ----------------
__global__ void __launch_bounds__(1024) stats2(const float* __restrict__ gamma,
                                               const float* __restrict__ beta) {
    __shared__ float sred[1024];
    int tid = threadIdx.x, c = tid & 255, sl = tid >> 8;   // 4 slices
    float acc = 0.f;
    #pragma unroll 8
    for (int p = sl; p < STAT_BLOCKS; p += 4) acc += g_part[p * 256 + c];
    sred[tid] = acc;
    __syncthreads();
    if (tid < 256) {
        float s = sred[tid] + sred[tid + 256] + sred[tid + 512] + sred[tid + 768];
        sred[tid] = s;
    }
    __syncthreads();
    if (tid < 128) {
        const float invN = 1.0f / (float)ROWS_TOT;
        float mean = sred[tid] * invN;
        float var  = sred[128 + tid] * invN - mean * mean;
        float a = gamma[tid] * rsqrtf(var + 1e-5f);
        g_ab[tid]       = a;
        g_ab[128 + tid] = beta[tid] - mean * a;
    }
}

// ---------------- GEMM m64 x n128 x k128, fp16 ----------------
__device__ __forceinline__ void gemm128(uint32_t aBase, uint32_t wBase,
                                        int mg, int ng, int lane, float acc[2][4][4]) {
    const int rowA  = mg * 32 + (lane & 15);
    const int rowN  = ng * 32 + (lane & 15);
    const uint32_t khalf = ((uint32_t)lane >> 4) * 16;
    #pragma unroll
    for (int ks = 0; ks < 8; ks++) {
        uint32_t a_[2][4], b_[2][4];
        uint32_t kb = (uint32_t)ks * 32 + khalf;
        #pragma unroll
        for (int mt = 0; mt < 2; mt++)
            LDSM4(a_[mt], aBase + swA((uint32_t)(rowA + mt * 16) * 256 + kb));
        #pragma unroll
        for (int xi = 0; xi < 2; xi++)
            LDSM4(b_[xi], wBase + swA((uint32_t)(rowN + xi * 16) * 256 + kb));
        #pragma unroll
        for (int mt = 0; mt < 2; mt++)
            #pragma unroll
            for (int xi = 0; xi < 2; xi++)
                #pragma unroll
                for (int hf = 0; hf < 2; hf++)
                    MMA(acc[mt][xi * 2 + hf], a_[mt], b_[xi][hf], b_[xi][hf + 2]);
    }
}

// accumulators -> fp16 buffer (272B row stride), then zero
__device__ __forceinline__ void acc_to_buf(char* smc, uint32_t boff,
                                           int mg, int ng, int lane, float acc[2][4][4]) {
    #pragma unroll
    for (int mt = 0; mt < 2; mt++)
        #pragma unroll
        for (int nt = 0; nt < 4; nt++) {
            int r   = mg * 32 + mt * 16 + (lane >> 2);
            int col = ng * 32 + nt * 8 + 2 * (lane & 3);
            float* a = acc[mt][nt];
            *(__half2*)(smc + boff + (uint32_t)r * 272 + (uint32_t)col * 2) =
                __floats2half2_rn(a[0], a[1]);
            *(__half2*)(smc + boff + (uint32_t)(r + 8) * 272 + (uint32_t)col * 2) =
                __floats2half2_rn(a[2], a[3]);
            a[0] = a[1] = a[2] = a[3] = 0.f;
        }
}

// ---------------- K3: fused pipeline ----------------
__global__ void __launch_bounds__(256, 2) fused(const float* __restrict__ x,
                                                const float* __restrict__ mask,
                                                const float* __restrict__ b_out,
                                                float* __restrict__ out) {
    extern __shared__ char smc[];
    const uint32_t sb = smem_u32(smc);
    const int tid = threadIdx.x, wid = tid >> 5, lane = tid & 31;
    const int mg = wid >> 2, ng = wid & 3;

    float* abf  = (float*)(smc + AB_OFF);
    float* bof  = (float*)(smc + BO_OFF);
    float* mskf = (float*)(smc + MSK_OFF);

    // prefetch weight slab 0 (Q chunk)
    uint4 pf[8];
    #pragma unroll
    for (int i = 0; i < 8; i++) pf[i] = g_w[tid + i * 256];

    abf[tid] = g_ab[tid];
    if (tid < 128) bof[tid] = b_out[tid];
    if (tid < 100) mskf[tid] = mask[tid];
    __syncthreads();

    const size_t grow0 = (size_t)blockIdx.x * 60;

    // ---- phase 1: x -> BN -> fp16 A tile (float4 loads) ----
    #pragma unroll
    for (int i = 0; i < 8; i++) {
        int idx = tid + i * 256;            // p 0..63, q4 0..31
        int p = idx >> 5, q4 = idx & 31;
        size_t real = grow0 + p;
        float4 v = make_float4(0.f, 0.f, 0.f, 0.f);
        if (p < 60 && real < ROWS_TOT)
            v = ((const float4*)(x + real * CH))[q4];
        int c = q4 * 4;
        float y0 = v.x * abf[c]     + abf[128 + c];
        float y1 = v.y * abf[c + 1] + abf[129 + c];
        float y2 = v.z * abf[c + 2] + abf[130 + c];
        float y3 = v.w * abf[c + 3] + abf[131 + c];
        uint2 pk;
        *(__half2*)&pk.x = __floats2half2_rn(y0, y1);
        *(__half2*)&pk.y = __floats2half2_rn(y2, y3);
        *(uint2*)(smc + A_OFF + swA((uint32_t)p * 256 + (uint32_t)c * 2)) = pk;
    }

    float acc[2][4][4];
    #pragma unroll
    for (int a1 = 0; a1 < 2; a1++)
        #pragma unroll
        for (int a2 = 0; a2 < 4; a2++)
            #pragma unroll
            for (int a3 = 0; a3 < 4; a3++) acc[a1][a2][a3] = 0.f;

    uint4* ws = (uint4*)(smc + W_OFF);
    const uint32_t aBase = sb + A_OFF, wBase = sb + W_OFF;

    // ---- phase 2: GEMM1 (Q,K,V chunks) ----
    for (int s = 0; s < 3; s++) {
        __syncthreads();
        #pragma unroll
        for (int i = 0; i < 8; i++) ws[tid + i * 256] = pf[i];
        #pragma unroll
        for (int i = 0; i < 8; i++) pf[i] = g_w[(s + 1) * 2048 + tid + i * 256];
        __syncthreads();
        gemm128(aBase, wBase, mg, ng, lane, acc);
        acc_to_buf(smc, QKV_OFF + s * QBUF_B, mg, ng, lane, acc);
    }
    __syncthreads();   // QKV complete, W + A regions free

    // ---- stage w_out slab now (hidden under attention) ----
    #pragma unroll
    for (int i = 0; i < 8; i++) ws[tid + i * 256] = pf[i];

    // ---- phase 3: attention, (r 0..63) x (h 0..7) over 2 rounds ----
    #pragma unroll
    for (int it = 0; it < 2; it++) {
        int t = tid + it * 256;
        int h = t >> 6, r = t & 63;
        size_t realr = grow0 + r;
        if (r < 60 && realr < ROWS_TOT) {
            int g = r / 10, vloc = r - g * 10;
            uint32_t hb = (uint32_t)h * 32;           // head byte offset in row
            const char* Qb = smc + QKV_OFF;
            const char* Kb = smc + QKV_OFF + QBUF_B;
            const char* Vb = smc + QKV_OFF + 2 * QBUF_B;
            float2 qf[8];
            ld8f(Qb + (uint32_t)r * 272 + hb,      qf);
            ld8f(Qb + (uint32_t)r * 272 + hb + 16, qf + 4);
            float dots[10];
            float sum = 0.f;
            #pragma unroll
            for (int j = 0; j < 10; j++) {
                const char* kr = Kb + (uint32_t)(g * 10 + j) * 272 + hb;
                float2 kf[8];
                ld8f(kr, kf);
                ld8f(kr + 16, kf + 4);
                float dd = 0.f;
                #pragma unroll
                for (int d = 0; d < 8; d++)
                    dd += qf[d].x * kf[d].x + qf[d].y * kf[d].y;
                dd = __expf(dd * 0.25f * mskf[vloc * 10 + j]);
                dots[j] = dd;
                sum += dd;
            }
            float inv = 1.0f / sum;
            float2 o[8];
            #pragma unroll
            for (int d = 0; d < 8; d++) o[d] = make_float2(0.f, 0.f);
            #pragma unroll
            for (int j = 0; j < 10; j++) {
                float pj = dots[j] * inv;
                const char* vr = Vb + (uint32_t)(g * 10 + j) * 272 + hb;
                float2 vf[8];
                ld8f(vr, vf);
                ld8f(vr + 16, vf + 4);
                #pragma unroll
                for (int d = 0; d < 8; d++) {
                    o[d].x += pj * vf[d].x;
                    o[d].y += pj * vf[d].y;
                }
            }
            // O -> A region (fp16, swA) as GEMM2 input: 2x16B stores
            uint4 pk0, pk1;
            *(__half2*)&pk0.x = __floats2half2_rn(o[0].x, o[0].y);
            *(__half2*)&pk0.y = __floats2half2_rn(o[1].x, o[1].y);
            *(__half2*)&pk0.z = __floats2half2_rn(o[2].x, o[2].y);
            *(__half2*)&pk0.w = __floats2half2_rn(o[3].x, o[3].y);
            *(__half2*)&pk1.x = __floats2half2_rn(o[4].x, o[4].y);
            *(__half2*)&pk1.y = __floats2half2_rn(o[5].x, o[5].y);
            *(__half2*)&pk1.z = __floats2half2_rn(o[6].x, o[6].y);
            *(__half2*)&pk1.w = __floats2half2_rn(o[7].x, o[7].y);
            *(uint4*)(smc + A_OFF + swA((uint32_t)r * 256 + hb))      = pk0;
            *(uint4*)(smc + A_OFF + swA((uint32_t)r * 256 + hb + 16)) = pk1;
        }
    }
    __syncthreads();

    // ---- phase 4: GEMM2 (out-proj) ----
    gemm128(aBase, wBase, mg, ng, lane, acc);

    // ---- phase 5: epilogue (bias + global store) ----
    #pragma unroll
    for (int mt = 0; mt < 2; mt++)
        #pragma unroll
        for (int nt = 0; nt < 4; nt++) {
            int r0 = mg * 32 + mt * 16 + (lane >> 2);
            int col = ng * 32 + nt * 8 + 2 * (lane & 3);
            float b0v = bof[col], b1v = bof[col + 1];
            float* a = acc[mt][nt];
            #pragma unroll
            for (int hf = 0; hf < 2; hf++) {
                int r = r0 + hf * 8;
                size_t real = grow0 + r;
                if (r < 60 && real < ROWS_TOT)
                    *(float2*)(out + real * CH + col) =
                        make_float2(a[2 * hf] + b0v, a[2 * hf + 1] + b1v);
            }
        }
}

// ---------------- launch ----------------
extern "C" void kernel_launch(void* const* d_in, const int* in_sizes, int n_in,
                              void* d_out, int out_size) {
    (void)in_sizes; (void)n_in; (void)out_size;
    const float* x     = (const float*)d_in[0];
    const float* gamma = (const float*)d_in[1];
    const float* beta  = (const float*)d_in[2];
    const float* w_qkv = (const float*)d_in[3];
    const float* w_out = (const float*)d_in[4];
    const float* b_out = (const float*)d_in[5];
    const float* mask  = (const float*)d_in[6];
    float* out = (float*)d_out;

    cudaFuncSetAttribute(fused, cudaFuncAttributeMaxDynamicSharedMemorySize, SMEM_TOTAL);

    prep_weights<<<256, 256>>>(w_qkv, w_out);
    stats1<<<STAT_BLOCKS, 256>>>(x);
    stats2<<<1, 1024>>>(gamma, beta);
    fused<<<NCTA, 256, SMEM_TOTAL>>>(x, mask, b_out, out);
}

// round 10
// speedup vs baseline: 3.4144x; 1.0021x over previous
#include <cuda_runtime.h>
#include <cuda_fp16.h>
#include <cstdint>

// ---------------- problem constants ----------------
#define ROWS_TOT  327680            // 32768 graphs * 10 nodes
#define CH        128
#define GR_CTA    6                 // graphs per CTA (60 rows -> padded M=64)
#define NCTA      ((32768 + GR_CTA - 1) / GR_CTA)   // 5462

// ---------------- smem layout (bytes) ----------------
#define A_OFF     0                 // 16KB fp16 swA: A (BN input) -> Q -> O
#define W_OFF     16384             // 16KB weight half-slab [n128][k64] sw128
#define K_OFF     32768             // 16KB fp16 swA: K buf
#define V_OFF     49152             // 16KB fp16 swA: V buf
#define AB_OFF    65536             // 256 floats
#define BO_OFF    66560             // 128 floats
#define MSK_OFF   67072             // 100 floats
#define SMEM_TOTAL 67584

#define STAT_BLOCKS 2048
#define ROWS_PER_STAT (ROWS_TOT / STAT_BLOCKS)   // 160

// ---------------- device globals ----------------
// 8 half-slabs of 16KB: slab = tile*2 + khalf, tile 0=Q,1=K,2=V,3=wout
// inner layout [n(128 rows)][k64 fp16 = 128B] with sw128 swizzle
__device__ uint4 g_w[8 * 1024];
__device__ float g_part[STAT_BLOCKS * 256];
__device__ float g_ab[256];

// ---------------- helpers ----------------
__device__ __forceinline__ uint32_t smem_u32(const void* p) {
    uint32_t a;
    asm("{ .reg .u64 t; cvta.to.shared.u64 t, %1; cvt.u32.u64 %0, t; }" : "=r"(a) : "l"(p));
    return a;
}
__device__ __forceinline__ uint32_t swA(uint32_t off)   { return off ^ ((off >> 4) & 0x70); } // 256B rows
__device__ __forceinline__ uint32_t sw128(uint32_t off) { return off ^ ((off >> 3) & 0x70); } // 128B rows

__device__ __forceinline__ void ld8f(const char* p, float2* f) {
    uint4 u = *(const uint4*)p;
    f[0] = __half22float2(*(__half2*)&u.x);
    f[1] = __half22float2(*(__half2*)&u.y);
    f[2] = __half22float2(*(__half2*)&u.z);
    f[3] = __half22float2(*(__half2*)&u.w);
}

__device__ __forceinline__ void cp16(uint32_t dst, const void* src) {
    asm volatile("cp.async.ca.shared.global [%0], [%1], 16;" :: "r"(dst), "l"(src));
}
#define CP_COMMIT() asm volatile("cp.async.commit_group;" ::: "memory")
#define CP_WAIT0()  asm volatile("cp.async.wait_group 0;" ::: "memory")

#define LDSM4(r, addr)                                                        \
    asm volatile("ldmatrix.sync.aligned.m8n8.x4.shared.b16 {%0,%1,%2,%3}, [%4];" \
                 : "=r"((r)[0]), "=r"((r)[1]), "=r"((r)[2]), "=r"((r)[3])     \
                 : "r"(addr))

#define MMA(d, a, b0v, b1v)                                                   \
    asm volatile("mma.sync.aligned.m16n8k16.row.col.f32.f16.f16.f32 "         \
                 "{%0,%1,%2,%3},{%4,%5,%6,%7},{%8,%9},{%0,%1,%2,%3};"         \
                 : "+f"((d)[0]), "+f"((d)[1]), "+f"((d)[2]), "+f"((d)[3])     \
                 : "r"((a)[0]), "r"((a)[1]), "r"((a)[2]), "r"((a)[3]),        \
                   "r"(b0v), "r"(b1v))

// ---------------- K0: fp16 + swizzle weights into half-slabs ----------------
__global__ void __launch_bounds__(256) prep_weights(const float* __restrict__ w_qkv,
                                                    const float* __restrict__ w_out) {
    int idx = blockIdx.x * 256 + threadIdx.x;          // 0..65535
    int tile = idx >> 14, rem = idx & 16383;
    int n = rem >> 7, k = rem & 127;
    float v = (tile < 3) ? w_qkv[k * 384 + tile * 128 + n] : w_out[k * 128 + n];
    int slab = tile * 2 + (k >> 6);
    uint32_t off = sw128((uint32_t)n * 128 + (uint32_t)(k & 63) * 2);
    *(__half*)((char*)g_w + slab * 16384 + off) = __float2half_rn(v);
}

// ---------------- K1: partial BN stats ----------------
__global__ void __launch_bounds__(256) stats1(const float* __restrict__ x) {
    __shared__ float red[2048];
    int tid = threadIdx.x, c4 = tid & 31, rg = tid >> 5;
    size_t r0 = (size_t)blockIdx.x * ROWS_PER_STAT;
    const float4* p = (const float4*)(x + r0 * CH) + c4;
    float sx = 0, sy = 0, sz = 0, sw = 0, qx = 0, qy = 0, qz = 0, qw = 0;
    #pragma unroll 10
    for (int r = rg; r < ROWS_PER_STAT; r += 8) {
        float4 v = p[(size_t)r * 32];
        sx += v.x; sy += v.y; sz += v.z; sw += v.w;
        qx += v.x * v.x; qy += v.y * v.y; qz += v.z * v.z; qw += v.w * v.w;
    }
    float* rr = red + tid * 8;
    rr[0] = sx; rr[1] = sy; rr[2] = sz; rr[3] = sw;
    rr[4] = qx; rr[5] = qy; rr[6] = qz; rr[7] = qw;
    __syncthreads();
    if (tid < 32) {
        float s[8] = {0, 0, 0, 0, 0, 0, 0, 0};
        for (int g = 0; g < 8; g++) {
            const float* r2 = red + (g * 32 + tid) * 8;
            #pragma unroll
            for (int i = 0; i < 8; i++) s[i] += r2[i];
        }
        #pragma unroll
        for (int i = 0; i < 4; i++) {
            g_part[blockIdx.x * 256 + tid * 4 + i]       = s[i];
            g_part[blockIdx.x * 256 + 128 + tid * 4 + i] = s[4 + i];
        }
    }
}

// ---------------- K2: finalize ----------------
__global__ void __launch_bounds__(1024) stats2(const float* __restrict__ gamma,
                                               const float* __restrict__ beta) {
    __shared__ float sred[1024];
    int tid = threadIdx.x, c = tid & 255, sl = tid >> 8;
    float acc = 0.f;
    #pragma unroll 8
    for (int p = sl; p < STAT_BLOCKS; p += 4) acc += g_part[p * 256 + c];
    sred[tid] = acc;
    __syncthreads();
    if (tid < 256)
        sred[tid] = sred[tid] + sred[tid + 256] + sred[tid + 512] + sred[tid + 768];
    __syncthreads();
    if (tid < 128) {
        const float invN = 1.0f / (float)ROWS_TOT;
        float mean = sred[tid] * invN;
        float var  = sred[128 + tid] * invN - mean * mean;
        float a = gamma[tid] * rsqrtf(var + 1e-5f);
        g_ab[tid]       = a;
        g_ab[128 + tid] = beta[tid] - mean * a;
    }
}

// ---------------- GEMM m64 x n128 x k64 over one weight half-slab ----------------
__device__ __forceinline__ void gemm64(uint32_t aBase, uint32_t wBase, uint32_t kbyte,
                                       int mg, int ng, int lane, float acc[2][4][4]) {
    const int rowA  = mg * 32 + (lane & 15);
    const int rowN  = ng * 32 + (lane & 15);
    const uint32_t kh = ((uint32_t)lane >> 4) * 16;
    #pragma unroll
    for (int ks = 0; ks < 4; ks++) {
        uint32_t a_[2][4], b_[2][4];
        #pragma unroll
        for (int mt = 0; mt < 2; mt++)
            LDSM4(a_[mt], aBase + swA((uint32_t)(rowA + mt * 16) * 256 + kbyte + ks * 32 + kh));
        #pragma unroll
        for (int xi = 0; xi < 2; xi++)
            LDSM4(b_[xi], wBase + sw128((uint32_t)(rowN + xi * 16) * 128 + ks * 32 + kh));
        #pragma unroll
        for (int mt = 0; mt < 2; mt++)
            #pragma unroll
            for (int xi = 0; xi < 2; xi++)
                #pragma unroll
                for (int hf = 0; hf < 2; hf++)
                    MMA(acc[mt][xi * 2 + hf], a_[mt], b_[xi][hf], b_[xi][hf + 2]);
    }
}

// accumulators -> fp16 buffer (256B rows, swA), then zero
__device__ __forceinline__ void acc_to_buf(char* smc, uint32_t boff,
                                           int mg, int ng, int lane, float acc[2][4][4]) {
    #pragma unroll
    for (int mt = 0; mt < 2; mt++)
        #pragma unroll
        for (int nt = 0; nt < 4; nt++) {
            int r   = mg * 32 + mt * 16 + (lane >> 2);
            int col = ng * 32 + nt * 8 + 2 * (lane & 3);
            float* a = acc[mt][nt];
            *(__half2*)(smc + boff + swA((uint32_t)r * 256 + (uint32_t)col * 2)) =
                __floats2half2_rn(a[0], a[1]);
            *(__half2*)(smc + boff + swA((uint32_t)(r + 8) * 256 + (uint32_t)col * 2)) =
                __floats2half2_rn(a[2], a[3]);
            a[0] = a[1] = a[2] = a[3] = 0.f;
        }
}

// copy one 16KB weight half-slab into W region via cp.async
__device__ __forceinline__ void copy_w(uint32_t sb, int slab, int tid) {
    const char* src = (const char*)g_w + slab * 16384;
    #pragma unroll
    for (int i = 0; i < 4; i++)
        cp16(sb + W_OFF + (uint32_t)(tid + i * 256) * 16, src + (tid + i * 256) * 16);
    CP_COMMIT();
}

// ---------------- K3: fused pipeline ----------------
__global__ void __launch_bounds__(256, 3) fused(const float* __restrict__ x,
                                                const float* __restrict__ mask,
                                                const float* __restrict__ b_out,
                                                float* __restrict__ out) {
    extern __shared__ char smc[];
    const uint32_t sb = smem_u32(smc);
    const int tid = threadIdx.x, wid = tid >> 5, lane = tid & 31;
    const int mg = wid >> 2, ng = wid & 3;

    float* abf  = (float*)(smc + AB_OFF);
    float* bof  = (float*)(smc + BO_OFF);
    float* mskf = (float*)(smc + MSK_OFF);

    abf[tid] = g_ab[tid];
    if (tid < 128) bof[tid] = b_out[tid];
    if (tid < 100) mskf[tid] = mask[tid];

    const size_t grow0 = (size_t)blockIdx.x * 60;

    // ---- phase 1: x -> BN -> fp16 A tile ----
    __syncthreads();
    #pragma unroll
    for (int i = 0; i < 8; i++) {
        int idx = tid + i * 256;            // p 0..63, q4 0..31
        int p = idx >> 5, q4 = idx & 31;
        size_t real = grow0 + p;
        float4 v = make_float4(0.f, 0.f, 0.f, 0.f);
        if (p < 60 && real < ROWS_TOT)
            v = ((const float4*)(x + real * CH))[q4];
        int c = q4 * 4;
        float y0 = v.x * abf[c]     + abf[128 + c];
        float y1 = v.y * abf[c + 1] + abf[129 + c];
        float y2 = v.z * abf[c + 2] + abf[130 + c];
        float y3 = v.w * abf[c + 3] + abf[131 + c];
        uint2 pk;
        *(__half2*)&pk.x = __floats2half2_rn(y0, y1);
        *(__half2*)&pk.y = __floats2half2_rn(y2, y3);
        *(uint2*)(smc + A_OFF + swA((uint32_t)p * 256 + (uint32_t)c * 2)) = pk;
    }
    __syncthreads();

    float acc[2][4][4];
    #pragma unroll
    for (int a1 = 0; a1 < 2; a1++)
        #pragma unroll
        for (int a2 = 0; a2 < 4; a2++)
            #pragma unroll
            for (int a3 = 0; a3 < 4; a3++) acc[a1][a2][a3] = 0.f;

    const uint32_t aBase = sb + A_OFF, wBase = sb + W_OFF;

    // ---- phase 2: GEMM1, tiles in order V(2), K(1), Q(0), two k-halves each ----
    #pragma unroll 1
    for (int i = 0; i < 6; i++) {
        const int tile = 2 - (i >> 1);          // 2,2,1,1,0,0
        const int half = i & 1;
        copy_w(sb, tile * 2 + half, tid);
        CP_WAIT0();
        __syncthreads();                         // W slab visible to all
        gemm64(aBase, wBase, (uint32_t)half * 128, mg, ng, lane, acc);
        __syncthreads();                         // all warps done with W (and A on last)
        if (i == 1) acc_to_buf(smc, V_OFF, mg, ng, lane, acc);
        else if (i == 3) acc_to_buf(smc, K_OFF, mg, ng, lane, acc);
        else if (i == 5) acc_to_buf(smc, A_OFF, mg, ng, lane, acc);   // Q overwrites A
    }

    // issue w_out half-0 copy now — hidden under attention
    copy_w(sb, 6, tid);
    __syncthreads();                             // Q/K/V buffers complete

    // ---- phase 3: attention, (r 0..63) x (h 0..7), online softmax accumulate ----
    #pragma unroll
    for (int it = 0; it < 2; it++) {
        int t = tid + it * 256;
        int h = t >> 6, r = t & 63;
        size_t realr = grow0 + r;
        if (r < 60 && realr < ROWS_TOT) {
            int g = r / 10, vloc = r - g * 10;
            uint32_t hb = (uint32_t)h * 32;
            float2 qf[8];
            ld8f(smc + A_OFF + swA((uint32_t)r * 256 + hb),      qf);
            ld8f(smc + A_OFF + swA((uint32_t)r * 256 + hb + 16), qf + 4);
            float sum = 0.f;
            float2 o[8];
            #pragma unroll
            for (int d = 0; d < 8; d++) o[d] = make_float2(0.f, 0.f);
            #pragma unroll
            for (int j = 0; j < 10; j++) {
                uint32_t rj = (uint32_t)(g * 10 + j) * 256 + hb;
                float2 kf[8];
                ld8f(smc + K_OFF + swA(rj),      kf);
                ld8f(smc + K_OFF + swA(rj + 16), kf + 4);
                float dd = 0.f;
                #pragma unroll
                for (int d = 0; d < 8; d++)
                    dd += qf[d].x * kf[d].x + qf[d].y * kf[d].y;
                float e = __expf(dd * 0.25f * mskf[vloc * 10 + j]);
                sum += e;
                float2 vf[8];
                ld8f(smc + V_OFF + swA(rj),      vf);
                ld8f(smc + V_OFF + swA(rj + 16), vf + 4);
                #pragma unroll
                for (int d = 0; d < 8; d++) {
                    o[d].x += e * vf[d].x;
                    o[d].y += e * vf[d].y;
                }
            }
            float inv = 1.0f / sum;
            uint4 pk0, pk1;
            *(__half2*)&pk0.x = __floats2half2_rn(o[0].x * inv, o[0].y * inv);
            *(__half2*)&pk0.y = __floats2half2_rn(o[1].x * inv, o[1].y * inv);
            *(__half2*)&pk0.z = __floats2half2_rn(o[2].x * inv, o[2].y * inv);
            *(__half2*)&pk0.w = __floats2half2_rn(o[3].x * inv, o[3].y * inv);
            *(__half2*)&pk1.x = __floats2half2_rn(o[4].x * inv, o[4].y * inv);
            *(__half2*)&pk1.y = __floats2half2_rn(o[5].x * inv, o[5].y * inv);
            *(__half2*)&pk1.z = __floats2half2_rn(o[6].x * inv, o[6].y * inv);
            *(__half2*)&pk1.w = __floats2half2_rn(o[7].x * inv, o[7].y * inv);
            *(uint4*)(smc + A_OFF + swA((uint32_t)r * 256 + hb))      = pk0;
            *(uint4*)(smc + A_OFF + swA((uint32_t)r * 256 + hb + 16)) = pk1;
        }
    }
    CP_WAIT0();
    __syncthreads();                             // O complete + w_out h0 staged

    // ---- phase 4: GEMM2 (out-proj), two k-halves ----
    gemm64(aBase, wBase, 0, mg, ng, lane, acc);
    __syncthreads();
    copy_w(sb, 7, tid);
    CP_WAIT0();
    __syncthreads();
    gemm64(aBase, wBase, 128, mg, ng, lane, acc);

    // ---- phase 5: epilogue (bias + global store) ----
    #pragma unroll
    for (int mt = 0; mt < 2; mt++)
        #pragma unroll
        for (int nt = 0; nt < 4; nt++) {
            int r0 = mg * 32 + mt * 16 + (lane >> 2);
            int col = ng * 32 + nt * 8 + 2 * (lane & 3);
            float b0v = bof[col], b1v = bof[col + 1];
            float* a = acc[mt][nt];
            #pragma unroll
            for (int hf = 0; hf < 2; hf++) {
                int r = r0 + hf * 8;
                size_t real = grow0 + r;
                if (r < 60 && real < ROWS_TOT)
                    *(float2*)(out + real * CH + col) =
                        make_float2(a[2 * hf] + b0v, a[2 * hf + 1] + b1v);
            }
        }
}

// ---------------- launch ----------------
extern "C" void kernel_launch(void* const* d_in, const int* in_sizes, int n_in,
                              void* d_out, int out_size) {
    (void)in_sizes; (void)n_in; (void)out_size;
    const float* x     = (const float*)d_in[0];
    const float* gamma = (const float*)d_in[1];
    const float* beta  = (const float*)d_in[2];
    const float* w_qkv = (const float*)d_in[3];
    const float* w_out = (const float*)d_in[4];
    const float* b_out = (const float*)d_in[5];
    const float* mask  = (const float*)d_in[6];
    float* out = (float*)d_out;

    cudaFuncSetAttribute(fused, cudaFuncAttributeMaxDynamicSharedMemorySize, SMEM_TOTAL);

    prep_weights<<<256, 256>>>(w_qkv, w_out);
    stats1<<<STAT_BLOCKS, 256>>>(x);
    stats2<<<1, 1024>>>(gamma, beta);
    fused<<<NCTA, 256, SMEM_TOTAL>>>(x, mask, b_out, out);
}